// round 1
// baseline (speedup 1.0000x reference)
#include <cuda_runtime.h>
#include <math_constants.h>
#include <stdint.h>

// Problem constants
#define HW    3600
#define WDIM  60
#define CCH   128          // channels (= K of the GEMM)
#define NBATCH 4           // batch pairs
#define KTOP  100
#define NBINS (1u << 20)
#define CAP   65536
#define NCHUNK 8           // row chunks for column stats

// ---------------- device scratch (static, no allocations) ----------------
__device__ float    g_sm[(size_t)NBATCH * HW * HW];   // 207 MB
__device__ float    g_LR[NBATCH * HW];                // rowmax + ln(rowsum)  (axis=2 softmax)
__device__ float    g_LC[NBATCH * HW];                // colmax + ln(colsum)  (axis=1 softmax)
__device__ float    g_pm[NBATCH * NCHUNK * HW];       // col partial max
__device__ float    g_ps[NBATCH * NCHUNK * HW];       // col partial sum
__device__ unsigned g_hist[NBATCH * NBINS];           // 16 MB
__device__ unsigned g_thr[NBATCH];
__device__ int      g_cnt[NBATCH];
__device__ float    g_cv[NBATCH * CAP];
__device__ int      g_ci[NBATCH * CAP];
__device__ int      g_topi[NBATCH * KTOP];
__device__ float    g_E[8 * CCH];
__device__ float    g_WX[CCH];
__device__ float    g_WY[CCH];

// ---------------- init ----------------
__global__ void zero_kernel() {
    unsigned idx = blockIdx.x * blockDim.x + threadIdx.x;
    if (idx < NBATCH * NBINS) g_hist[idx] = 0u;
    if (idx < NBATCH) g_cnt[idx] = 0;
}

// ---------------- GEMM: sm[n,l,s] = sum_d x0[n,d,l]*x1[n,d,s] / 12.8 ----------------
// x layout: (8, 128, 3600); x0 = batches 0..3, x1 = batches 4..7.
// A[d][l] and B[d][s] are both row-contiguous in l/s -> no transpose needed.
__global__ __launch_bounds__(256) void gemm_kernel(const float* __restrict__ x) {
    const int n  = blockIdx.z;
    const int l0 = blockIdx.y * 128;
    const int s0 = blockIdx.x * 128;
    const float* A = x + (size_t)n * CCH * HW;
    const float* B = x + (size_t)(n + NBATCH) * CCH * HW;

    __shared__ float As[16][128];
    __shared__ float Bs[16][128];

    const int tid = threadIdx.x;
    const int tx = tid & 15, ty = tid >> 4;
    const int lr = tid >> 5;          // 0..7 (load row)
    const int lc = (tid & 31) << 2;   // 0..124 step 4 (load col, float4)

    float acc[8][8];
#pragma unroll
    for (int i = 0; i < 8; i++)
#pragma unroll
        for (int j = 0; j < 8; j++) acc[i][j] = 0.0f;

    for (int k0 = 0; k0 < CCH; k0 += 16) {
#pragma unroll
        for (int r = 0; r < 2; r++) {
            const int d = lr + r * 8;
            float4 va = make_float4(0.f, 0.f, 0.f, 0.f);
            float4 vb = make_float4(0.f, 0.f, 0.f, 0.f);
            const int gl = l0 + lc;
            const int gs = s0 + lc;
            // HW % 4 == 0 and lc % 4 == 0 -> a float4 never straddles the boundary
            if (gl < HW) va = *reinterpret_cast<const float4*>(A + (size_t)(k0 + d) * HW + gl);
            if (gs < HW) vb = *reinterpret_cast<const float4*>(B + (size_t)(k0 + d) * HW + gs);
            *reinterpret_cast<float4*>(&As[d][lc]) = va;
            *reinterpret_cast<float4*>(&Bs[d][lc]) = vb;
        }
        __syncthreads();
#pragma unroll
        for (int d = 0; d < 16; d++) {
            float a[8], bb[8];
            *reinterpret_cast<float4*>(&a[0]) = *reinterpret_cast<const float4*>(&As[d][ty * 4]);
            *reinterpret_cast<float4*>(&a[4]) = *reinterpret_cast<const float4*>(&As[d][64 + ty * 4]);
            *reinterpret_cast<float4*>(&bb[0]) = *reinterpret_cast<const float4*>(&Bs[d][tx * 4]);
            *reinterpret_cast<float4*>(&bb[4]) = *reinterpret_cast<const float4*>(&Bs[d][64 + tx * 4]);
#pragma unroll
            for (int i = 0; i < 8; i++)
#pragma unroll
                for (int j = 0; j < 8; j++)
                    acc[i][j] = fmaf(a[i], bb[j], acc[i][j]);
        }
        __syncthreads();
    }

#pragma unroll
    for (int i = 0; i < 8; i++) {
        const int li = l0 + ((i < 4) ? (ty * 4 + i) : (64 + ty * 4 + i - 4));
        if (li >= HW) continue;
        float* orow = g_sm + ((size_t)(n * HW + li)) * HW;
        const int sj0 = s0 + tx * 4;
        if (sj0 < HW) {
            float4 v = make_float4(acc[i][0] / 12.8f, acc[i][1] / 12.8f,
                                   acc[i][2] / 12.8f, acc[i][3] / 12.8f);
            *reinterpret_cast<float4*>(orow + sj0) = v;
        }
        const int sj1 = s0 + 64 + tx * 4;
        if (sj1 < HW) {
            float4 v = make_float4(acc[i][4] / 12.8f, acc[i][5] / 12.8f,
                                   acc[i][6] / 12.8f, acc[i][7] / 12.8f);
            *reinterpret_cast<float4*>(orow + sj1) = v;
        }
    }
}

// ---------------- row stats (softmax over s, axis=2): LR[l] = max + ln(sumexp) ----------------
__global__ __launch_bounds__(256) void row_stats_kernel() {
    __shared__ float buf[HW];
    __shared__ float red[256];
    const int n = blockIdx.y, l = blockIdx.x;
    const float* row = g_sm + ((size_t)(n * HW + l)) * HW;
    const int tid = threadIdx.x;

    float m = -CUDART_INF_F;
    for (int s = tid; s < HW; s += 256) {
        float v = row[s];
        buf[s] = v;
        m = fmaxf(m, v);
    }
    red[tid] = m;
    __syncthreads();
    for (int o = 128; o > 0; o >>= 1) {
        if (tid < o) red[tid] = fmaxf(red[tid], red[tid + o]);
        __syncthreads();
    }
    const float rmax = red[0];
    __syncthreads();
    float sum = 0.0f;
    for (int s = tid; s < HW; s += 256) sum += expf(buf[s] - rmax);
    red[tid] = sum;
    __syncthreads();
    for (int o = 128; o > 0; o >>= 1) {
        if (tid < o) red[tid] += red[tid + o];
        __syncthreads();
    }
    if (tid == 0) g_LR[n * HW + l] = rmax + logf(red[0]);
}

// ---------------- column stats (softmax over l, axis=1), online, chunked ----------------
__global__ __launch_bounds__(128) void col_partial_kernel() {
    const int n = blockIdx.z, chunk = blockIdx.y;
    const int s = blockIdx.x * 128 + threadIdx.x;
    if (s >= HW) return;
    const int rows = HW / NCHUNK;  // 450
    const float* base = g_sm + (size_t)n * HW * HW + (size_t)chunk * rows * HW + s;
    float m = -CUDART_INF_F, sum = 0.0f;
    for (int l = 0; l < rows; l++) {
        float v = base[(size_t)l * HW];
        if (v > m) {
            sum = sum * expf(m - v) + 1.0f;   // expf(-inf)=0 handles first iter
            m = v;
        } else {
            sum += expf(v - m);
        }
    }
    g_pm[(n * NCHUNK + chunk) * HW + s] = m;
    g_ps[(n * NCHUNK + chunk) * HW + s] = sum;
}

__global__ __launch_bounds__(256) void col_merge_kernel() {
    const int n = blockIdx.y;
    const int s = blockIdx.x * 256 + threadIdx.x;
    if (s >= HW) return;
    float m = -CUDART_INF_F;
#pragma unroll
    for (int c = 0; c < NCHUNK; c++) m = fmaxf(m, g_pm[(n * NCHUNK + c) * HW + s]);
    float sum = 0.0f;
#pragma unroll
    for (int c = 0; c < NCHUNK; c++)
        sum += g_ps[(n * NCHUNK + c) * HW + s] * expf(g_pm[(n * NCHUNK + c) * HW + s] - m);
    g_LC[n * HW + s] = m + logf(sum);
}

// ---------------- ranking score: ln(cm) = 2v - LR[l] - LC[s]  (monotone in cm) ----------------
__device__ __forceinline__ float score_at(int n, int l, int s, float v) {
    return __fmaf_rn(2.0f, v, -g_LR[n * HW + l]) - g_LC[n * HW + s];
}
__device__ __forceinline__ unsigned mono_bits(float f) {
    unsigned b = __float_as_uint(f);
    return (b & 0x80000000u) ? ~b : (b | 0x80000000u);
}

__global__ __launch_bounds__(256) void hist_kernel() {
    const int n = blockIdx.y, l = blockIdx.x;
    const float* row = g_sm + ((size_t)(n * HW + l)) * HW;
    unsigned* hist = g_hist + (size_t)n * NBINS;
    for (int s = threadIdx.x; s < HW; s += 256) {
        float sc = score_at(n, l, s, row[s]);
        atomicAdd(&hist[mono_bits(sc) >> 12], 1u);
    }
}

__global__ __launch_bounds__(256) void thresh_kernel() {
    const int n = blockIdx.x;
    const unsigned* h = g_hist + (size_t)n * NBINS;
    __shared__ unsigned lvl[256];
    __shared__ int selc;
    __shared__ unsigned carry;
    const int tid = threadIdx.x;
    const int CH = NBINS / 256;  // 4096

    unsigned t = 0;
    for (int i = 0; i < CH; i += 4) {
        uint4 v = *reinterpret_cast<const uint4*>(h + tid * CH + i);
        t += v.x + v.y + v.z + v.w;
    }
    lvl[tid] = t;
    __syncthreads();
    if (tid == 0) {
        unsigned cum = 0; int c = 255;
        while (c > 0 && cum + lvl[c] < KTOP) { cum += lvl[c]; c--; }
        selc = c; carry = cum;
    }
    __syncthreads();
    const int base = selc * CH;
    unsigned t2 = 0;
    for (int i = 0; i < 16; i += 4) {
        uint4 v = *reinterpret_cast<const uint4*>(h + base + tid * 16 + i);
        t2 += v.x + v.y + v.z + v.w;
    }
    __syncthreads();
    lvl[tid] = t2;
    __syncthreads();
    if (tid == 0) {
        unsigned cum = carry; int c = 255;
        while (c > 0 && cum + lvl[c] < KTOP) { cum += lvl[c]; c--; }
        int b = base + c * 16 + 15;
        const int bend = base + c * 16;
        while (b > bend && cum + h[b] < KTOP) { cum += h[b]; b--; }
        g_thr[n] = (unsigned)b;
    }
}

__global__ __launch_bounds__(256) void collect_kernel() {
    const int n = blockIdx.y, l = blockIdx.x;
    const float* row = g_sm + ((size_t)(n * HW + l)) * HW;
    const unsigned thr = g_thr[n];
    for (int s = threadIdx.x; s < HW; s += 256) {
        float sc = score_at(n, l, s, row[s]);
        if ((mono_bits(sc) >> 12) >= thr) {
            int p = atomicAdd(&g_cnt[n], 1);
            if (p < CAP) {
                g_cv[n * CAP + p] = sc;
                g_ci[n * CAP + p] = l * HW + s;
            }
        }
    }
}

// ---------------- exact sorted top-100 (value desc, index asc ties) ----------------
__global__ __launch_bounds__(256) void select_kernel() {
    const int n = blockIdx.x;
    const int tid = threadIdx.x;
    int cnt = g_cnt[n];
    if (cnt > CAP) cnt = CAP;
    float* cv = g_cv + n * CAP;
    int* ci = g_ci + n * CAP;
    __shared__ float sv[256];
    __shared__ int si[256];
    __shared__ int sp[256];

    for (int k = 0; k < KTOP; k++) {
        float bv = -CUDART_INF_F; int bi = 0x7FFFFFFF; int bp = -1;
        for (int j = tid; j < cnt; j += 256) {
            float v = cv[j]; int idx = ci[j];
            if (v > bv || (v == bv && idx < bi)) { bv = v; bi = idx; bp = j; }
        }
        sv[tid] = bv; si[tid] = bi; sp[tid] = bp;
        __syncthreads();
        for (int o = 128; o > 0; o >>= 1) {
            if (tid < o) {
                if (sv[tid + o] > sv[tid] || (sv[tid + o] == sv[tid] && si[tid + o] < si[tid])) {
                    sv[tid] = sv[tid + o]; si[tid] = si[tid + o]; sp[tid] = sp[tid + o];
                }
            }
            __syncthreads();
        }
        if (tid == 0) {
            g_topi[n * KTOP + k] = si[0];
            if (sp[0] >= 0) cv[sp[0]] = -CUDART_INF_F;
        }
        __syncthreads();
    }
}

// ---------------- embedding closed form: per (out-batch, d) constants ----------------
__global__ __launch_bounds__(128) void prep_kernel(const float* __restrict__ W) {
    const int np = blockIdx.x;   // 0..7 output batch
    const int d = threadIdx.x;   // 0..127
    const int n = np & 3;
    const bool side1 = (np >= 4);
    float S = 0.0f, wx = 0.0f, wy = 0.0f;
    for (int k = 0; k < KTOP; k++) {
        int idx = g_topi[n * KTOP + k];
        int r = side1 ? (idx % HW) : (idx / HW);
        float cx = (float)(r % WDIM) / 60.0f;
        float cy = (float)(r / WDIM) / 60.0f;
        float w0 = W[d * (2 * KTOP) + 2 * k];
        float w1 = W[d * (2 * KTOP) + 2 * k + 1];
        S = fmaf(w0, cx, S);
        S = fmaf(w1, cy, S);
        wx += w0; wy += w1;
    }
    g_E[np * CCH + d] = -S;
    if (np == 0) { g_WX[d] = wx; g_WY[d] = wy; }
}

// ---------------- final: out = x + gx*WX + gy*WY + E + b ----------------
__global__ __launch_bounds__(256) void final_kernel(const float* __restrict__ x,
                                                    const float* __restrict__ bvec,
                                                    float* __restrict__ out) {
    const int d = blockIdx.x;
    const int np = blockIdx.y;
    const float wx = g_WX[d];
    const float wy = g_WY[d];
    const float e = g_E[np * CCH + d] + bvec[d];
    const size_t base = ((size_t)np * CCH + d) * HW;
    for (int p = threadIdx.x; p < HW; p += 256) {
        float gx = (float)(p % WDIM) / 60.0f;
        float gy = (float)(p / WDIM) / 60.0f;
        out[base + p] = x[base + p] + gx * wx + gy * wy + e;
    }
}

// ---------------- launch ----------------
extern "C" void kernel_launch(void* const* d_in, const int* in_sizes, int n_in,
                              void* d_out, int out_size) {
    (void)in_sizes; (void)n_in; (void)out_size;
    const float* x = (const float*)d_in[0];
    const float* W = (const float*)d_in[1];
    const float* b = (const float*)d_in[2];
    float* out = (float*)d_out;

    zero_kernel<<<(NBATCH * NBINS + 1023) / 1024, 1024>>>();

    dim3 gg((HW + 127) / 128, (HW + 127) / 128, NBATCH);
    gemm_kernel<<<gg, 256>>>(x);

    row_stats_kernel<<<dim3(HW, NBATCH), 256>>>();
    col_partial_kernel<<<dim3((HW + 127) / 128, NCHUNK, NBATCH), 128>>>();
    col_merge_kernel<<<dim3((HW + 255) / 256, NBATCH), 256>>>();

    hist_kernel<<<dim3(HW, NBATCH), 256>>>();
    thresh_kernel<<<NBATCH, 256>>>();
    collect_kernel<<<dim3(HW, NBATCH), 256>>>();
    select_kernel<<<NBATCH, 256>>>();

    prep_kernel<<<8, 128>>>(W);
    final_kernel<<<dim3(CCH, 8), 256>>>(x, b, out);
}

// round 2
// speedup vs baseline: 12.5457x; 12.5457x over previous
#include <cuda_runtime.h>
#include <math_constants.h>
#include <stdint.h>

#define HW    3600
#define WDIM  60
#define CCH   128
#define NBATCH 4
#define KTOP  100
#define CAP   65536
#define NBX   29          // ceil(3600/128)
#define BM    128
#define BN    128
#define BK    16
#define LCPARTS 15        // ceil(3600/256)

// ---------------- device scratch ----------------
__device__ float g_sm[(size_t)NBATCH * HW * HW];   // 207 MB
__device__ float g_rp[NBATCH * NBX * HW];          // exp row partials per col-block
__device__ float g_cp[NBATCH * NBX * HW];          // exp col partials per row-block
__device__ float g_vp[NBATCH * NBX * HW];          // row vmax partials per col-block
__device__ float g_LR[NBATCH * HW];
__device__ float g_LC[NBATCH * HW];
__device__ float g_vmax[NBATCH * HW];
__device__ float g_lcmin_part[NBATCH * LCPARTS];
__device__ float g_lcmax_part[NBATCH * LCPARTS];
__device__ float g_thrv[NBATCH];
__device__ float g_lcmin[NBATCH];
__device__ int   g_cnt[NBATCH];
__device__ float g_cv[NBATCH * CAP];
__device__ int   g_ci[NBATCH * CAP];
__device__ int   g_topi[NBATCH * KTOP];
__device__ float g_E[8 * CCH];
__device__ float g_WX[CCH];
__device__ float g_WY[CCH];

// ---------------- cp.async helper ----------------
__device__ __forceinline__ void cp16(float* dst_smem, const float* src, bool ok) {
    unsigned d = (unsigned)__cvta_generic_to_shared(dst_smem);
    int sz = ok ? 16 : 0;
    asm volatile("cp.async.ca.shared.global [%0], [%1], 16, %2;\n" :: "r"(d), "l"(src), "r"(sz));
}
__device__ __forceinline__ void cp_commit() { asm volatile("cp.async.commit_group;\n"); }
__device__ __forceinline__ void cp_wait0()  { asm volatile("cp.async.wait_group 0;\n"); }

// ---------------- GEMM + fused exp-stats epilogue ----------------
// sm[n,l,s] = sum_d x0[n,d,l]*x1[n,d,s] / 12.8 ; also per-block partials of
// rowsumexp, colsumexp, rowmax(v), deterministic merge later.
__global__ __launch_bounds__(256, 2) void gemm_kernel(const float* __restrict__ x) {
    __shared__ float As[2][BK][BM];
    __shared__ float Bs[2][BK][BN];
    __shared__ float cred[8][128];

    const int n  = blockIdx.z;
    const int l0 = blockIdx.y * BM;
    const int s0 = blockIdx.x * BN;
    const float* A = x + (size_t)n * CCH * HW;
    const float* B = x + (size_t)(n + NBATCH) * CCH * HW;
    const int tid = threadIdx.x;
    const int tx = tid & 15, ty = tid >> 4;

    float acc[8][8];
#pragma unroll
    for (int i = 0; i < 8; i++)
#pragma unroll
        for (int j = 0; j < 8; j++) acc[i][j] = 0.0f;

    // ---- prefetch chunk 0 ----
    {
        const int kc = 0, st = 0;
#pragma unroll
        for (int i = 0; i < 2; i++) {
            int f = tid + i * 256;          // 0..511
            int d = f >> 5;                 // 0..15
            int c4 = (f & 31) << 2;         // 0..124
            int colA = l0 + c4; bool okA = colA < HW;
            cp16(&As[st][d][c4], A + (size_t)(kc * BK + d) * HW + (okA ? colA : 0), okA);
            int colB = s0 + c4; bool okB = colB < HW;
            cp16(&Bs[st][d][c4], B + (size_t)(kc * BK + d) * HW + (okB ? colB : 0), okB);
        }
        cp_commit();
    }

    for (int c = 0; c < CCH / BK; c++) {
        cp_wait0();
        __syncthreads();
        if (c < CCH / BK - 1) {
            const int kc = c + 1, st = (c + 1) & 1;
#pragma unroll
            for (int i = 0; i < 2; i++) {
                int f = tid + i * 256;
                int d = f >> 5;
                int c4 = (f & 31) << 2;
                int colA = l0 + c4; bool okA = colA < HW;
                cp16(&As[st][d][c4], A + (size_t)(kc * BK + d) * HW + (okA ? colA : 0), okA);
                int colB = s0 + c4; bool okB = colB < HW;
                cp16(&Bs[st][d][c4], B + (size_t)(kc * BK + d) * HW + (okB ? colB : 0), okB);
            }
            cp_commit();
        }
        const int st = c & 1;
#pragma unroll
        for (int d = 0; d < BK; d++) {
            float a[8], b[8];
            *reinterpret_cast<float4*>(&a[0]) = *reinterpret_cast<const float4*>(&As[st][d][ty * 4]);
            *reinterpret_cast<float4*>(&a[4]) = *reinterpret_cast<const float4*>(&As[st][d][64 + ty * 4]);
            *reinterpret_cast<float4*>(&b[0]) = *reinterpret_cast<const float4*>(&Bs[st][d][tx * 4]);
            *reinterpret_cast<float4*>(&b[4]) = *reinterpret_cast<const float4*>(&Bs[st][d][64 + tx * 4]);
#pragma unroll
            for (int i = 0; i < 8; i++)
#pragma unroll
                for (int j = 0; j < 8; j++)
                    acc[i][j] = fmaf(a[i], b[j], acc[i][j]);
        }
        // next iteration's top-of-loop __syncthreads separates this compute
        // from the overwrite of stage st (issued at iteration c+1).
    }

    // ---- epilogue: scale, store, exp stats ----
    int liv[8];
#pragma unroll
    for (int i = 0; i < 8; i++) liv[i] = l0 + ((i < 4) ? (ty * 4 + i) : (64 + ty * 4 + i - 4));

    float rowsum[8], rowmx[8], colsum[8];
#pragma unroll
    for (int i = 0; i < 8; i++) { rowsum[i] = 0.0f; rowmx[i] = -CUDART_INF_F; colsum[i] = 0.0f; }

#pragma unroll
    for (int i = 0; i < 8; i++) {
        const int li = liv[i];
        if (li >= HW) continue;
        float v[8];
#pragma unroll
        for (int j = 0; j < 8; j++) v[j] = acc[i][j] / 12.8f;
        float* orow = g_sm + ((size_t)(n * HW + li)) * HW;
        const int sj0 = s0 + tx * 4;
        if (sj0 < HW) *reinterpret_cast<float4*>(orow + sj0) = make_float4(v[0], v[1], v[2], v[3]);
        const int sj1 = s0 + 64 + tx * 4;
        if (sj1 < HW) *reinterpret_cast<float4*>(orow + sj1) = make_float4(v[4], v[5], v[6], v[7]);
#pragma unroll
        for (int j = 0; j < 8; j++) {
            const int sj = s0 + ((j < 4) ? (tx * 4 + j) : (64 + tx * 4 + j - 4));
            if (sj < HW) {
                float e = expf(v[j]);
                rowsum[i] += e;
                colsum[j] += e;
                rowmx[i] = fmaxf(rowmx[i], v[j]);
            }
        }
    }

    // row reductions across tx (16-lane halves of each warp)
#pragma unroll
    for (int m = 1; m < 16; m <<= 1) {
#pragma unroll
        for (int i = 0; i < 8; i++) {
            rowsum[i] += __shfl_xor_sync(0xffffffffu, rowsum[i], m);
            rowmx[i]  = fmaxf(rowmx[i], __shfl_xor_sync(0xffffffffu, rowmx[i], m));
        }
    }
    const int lane = tid & 31;
    const int w = tid >> 5;
    if ((lane & 15) == 0) {
#pragma unroll
        for (int i = 0; i < 8; i++) {
            if (liv[i] < HW) {
                g_rp[(n * NBX + blockIdx.x) * HW + liv[i]] = rowsum[i];
                g_vp[(n * NBX + blockIdx.x) * HW + liv[i]] = rowmx[i];
            }
        }
    }

    // col reduction: merge the 2 ty-groups per warp, then across warps in smem
#pragma unroll
    for (int j = 0; j < 8; j++) colsum[j] += __shfl_xor_sync(0xffffffffu, colsum[j], 16);
    if (lane < 16) {
#pragma unroll
        for (int j = 0; j < 8; j++) {
            const int col = (j < 4) ? (lane * 4 + j) : (64 + lane * 4 + j - 4);
            cred[w][col] = colsum[j];
        }
    }
    __syncthreads();
    if (tid < 128) {
        float sc = 0.0f;
#pragma unroll
        for (int w2 = 0; w2 < 8; w2++) sc += cred[w2][tid];
        const int s = s0 + tid;
        if (s < HW) g_cp[(n * NBX + blockIdx.y) * HW + s] = sc;
    }
}

// ---------------- merge: LR, vmax ----------------
__global__ __launch_bounds__(256) void rowfin_kernel() {
    const int n = blockIdx.y;
    const int l = blockIdx.x * 256 + threadIdx.x;
    if (l >= HW) return;
    float s = 0.0f, m = -CUDART_INF_F;
#pragma unroll
    for (int b = 0; b < NBX; b++) {
        s += g_rp[(n * NBX + b) * HW + l];
        m = fmaxf(m, g_vp[(n * NBX + b) * HW + l]);
    }
    g_LR[n * HW + l] = logf(s);
    g_vmax[n * HW + l] = m;
}

// ---------------- merge: LC + per-block min/max ----------------
__global__ __launch_bounds__(256) void colfin_kernel() {
    const int n = blockIdx.y;
    const int s = blockIdx.x * 256 + threadIdx.x;
    __shared__ float mn[256], mx[256];
    float lo = CUDART_INF_F, hi = -CUDART_INF_F;
    if (s < HW) {
        float acc = 0.0f;
#pragma unroll
        for (int b = 0; b < NBX; b++) acc += g_cp[(n * NBX + b) * HW + s];
        float v = logf(acc);
        g_LC[n * HW + s] = v;
        lo = v; hi = v;
    }
    const int tid = threadIdx.x;
    mn[tid] = lo; mx[tid] = hi;
    __syncthreads();
    for (int o = 128; o > 0; o >>= 1) {
        if (tid < o) {
            mn[tid] = fminf(mn[tid], mn[tid + o]);
            mx[tid] = fmaxf(mx[tid], mx[tid + o]);
        }
        __syncthreads();
    }
    if (tid == 0) {
        g_lcmin_part[n * LCPARTS + blockIdx.x] = mn[0];
        g_lcmax_part[n * LCPARTS + blockIdx.x] = mx[0];
    }
}

// ---------------- threshold from per-row score lower bounds ----------------
__global__ __launch_bounds__(256) void bound_kernel() {
    const int n = blockIdx.x;
    const int tid = threadIdx.x;
    __shared__ float s_lcmax;
    __shared__ float red1[256], red2[256];
    __shared__ int hist[2048];
    __shared__ float s_lmn, s_lmx;

    if (tid == 0) {
        float mn = CUDART_INF_F, mx = -CUDART_INF_F;
        for (int i = 0; i < LCPARTS; i++) {
            mn = fminf(mn, g_lcmin_part[n * LCPARTS + i]);
            mx = fmaxf(mx, g_lcmax_part[n * LCPARTS + i]);
        }
        g_lcmin[n] = mn;
        s_lcmax = mx;
        g_cnt[n] = 0;
    }
    __syncthreads();
    const float lcmax = s_lcmax;

    float lmn = CUDART_INF_F, lmx = -CUDART_INF_F;
    for (int l = tid; l < HW; l += 256) {
        float L = fmaf(2.0f, g_vmax[n * HW + l], -g_LR[n * HW + l]) - lcmax;
        lmn = fminf(lmn, L); lmx = fmaxf(lmx, L);
    }
    red1[tid] = lmn; red2[tid] = lmx;
    __syncthreads();
    for (int o = 128; o > 0; o >>= 1) {
        if (tid < o) {
            red1[tid] = fminf(red1[tid], red1[tid + o]);
            red2[tid] = fmaxf(red2[tid], red2[tid + o]);
        }
        __syncthreads();
    }
    if (tid == 0) { s_lmn = red1[0]; s_lmx = red2[0]; }
    __syncthreads();
    const float Lmn = s_lmn;
    const float binw = (s_lmx - Lmn) * (1.0f / 2048.0f);
    if (binw < 1e-30f) {
        if (tid == 0) g_thrv[n] = Lmn;
        return;
    }
    for (int i = tid; i < 2048; i += 256) hist[i] = 0;
    __syncthreads();
    for (int l = tid; l < HW; l += 256) {
        float L = fmaf(2.0f, g_vmax[n * HW + l], -g_LR[n * HW + l]) - lcmax;
        int b = (int)((L - Lmn) / binw);
        b = max(0, min(2047, b));
        atomicAdd(&hist[b], 1);
    }
    __syncthreads();
    if (tid == 0) {
        int cum = 0, b = 2047;
        for (; b >= 0; b--) { cum += hist[b]; if (cum >= KTOP) break; }
        if (b < 0) b = 0;
        g_thrv[n] = Lmn + (float)(b - 1) * binw;   // one-bin safety margin
    }
}

// ---------------- collect candidates (only flagged rows) ----------------
__global__ __launch_bounds__(128) void collect_kernel() {
    const int n = blockIdx.y, l = blockIdx.x;
    const float t = g_thrv[n];
    const float LR = g_LR[n * HW + l];
    const float Bnd = fmaf(2.0f, g_vmax[n * HW + l], -LR) - g_lcmin[n];
    if (Bnd < t) return;
    const float* row = g_sm + ((size_t)(n * HW + l)) * HW;
    const float* LC = g_LC + n * HW;
    for (int s4 = threadIdx.x * 4; s4 < HW; s4 += 128 * 4) {
        float4 v = *reinterpret_cast<const float4*>(row + s4);
        float4 c = *reinterpret_cast<const float4*>(LC + s4);
        float sc[4];
        sc[0] = fmaf(2.0f, v.x, -LR) - c.x;
        sc[1] = fmaf(2.0f, v.y, -LR) - c.y;
        sc[2] = fmaf(2.0f, v.z, -LR) - c.z;
        sc[3] = fmaf(2.0f, v.w, -LR) - c.w;
#pragma unroll
        for (int q = 0; q < 4; q++) {
            if (sc[q] >= t) {
                int p = atomicAdd(&g_cnt[n], 1);
                if (p < CAP) {
                    g_cv[n * CAP + p] = sc[q];
                    g_ci[n * CAP + p] = l * HW + s4 + q;
                }
            }
        }
    }
}

// ---------------- exact sorted top-100 (value desc, index asc ties) ----------------
__global__ __launch_bounds__(256) void select_kernel() {
    const int n = blockIdx.x;
    const int tid = threadIdx.x;
    int cnt = g_cnt[n];
    if (cnt > CAP) cnt = CAP;
    float* cv = g_cv + n * CAP;
    int* ci = g_ci + n * CAP;
    __shared__ float sv[256];
    __shared__ int si[256];
    __shared__ int sp[256];

    for (int k = 0; k < KTOP; k++) {
        float bv = -CUDART_INF_F; int bi = 0x7FFFFFFF; int bp = -1;
        for (int j = tid; j < cnt; j += 256) {
            float v = cv[j]; int idx = ci[j];
            if (v > bv || (v == bv && idx < bi)) { bv = v; bi = idx; bp = j; }
        }
        sv[tid] = bv; si[tid] = bi; sp[tid] = bp;
        __syncthreads();
        for (int o = 128; o > 0; o >>= 1) {
            if (tid < o) {
                if (sv[tid + o] > sv[tid] || (sv[tid + o] == sv[tid] && si[tid + o] < si[tid])) {
                    sv[tid] = sv[tid + o]; si[tid] = si[tid + o]; sp[tid] = sp[tid + o];
                }
            }
            __syncthreads();
        }
        if (tid == 0) {
            g_topi[n * KTOP + k] = si[0];
            if (sp[0] >= 0) cv[sp[0]] = -CUDART_INF_F;
        }
        __syncthreads();
    }
}

// ---------------- embedding closed form ----------------
__global__ __launch_bounds__(128) void prep_kernel(const float* __restrict__ W) {
    const int np = blockIdx.x;   // 0..7
    const int d = threadIdx.x;   // 0..127
    const int n = np & 3;
    const bool side1 = (np >= 4);
    float S = 0.0f, wx = 0.0f, wy = 0.0f;
    for (int k = 0; k < KTOP; k++) {
        int idx = g_topi[n * KTOP + k];
        int r = side1 ? (idx % HW) : (idx / HW);
        float cx = (float)(r % WDIM) / 60.0f;
        float cy = (float)(r / WDIM) / 60.0f;
        float w0 = W[d * (2 * KTOP) + 2 * k];
        float w1 = W[d * (2 * KTOP) + 2 * k + 1];
        S = fmaf(w0, cx, S);
        S = fmaf(w1, cy, S);
        wx += w0; wy += w1;
    }
    g_E[np * CCH + d] = -S;
    if (np == 0) { g_WX[d] = wx; g_WY[d] = wy; }
}

__global__ __launch_bounds__(256) void final_kernel(const float* __restrict__ x,
                                                    const float* __restrict__ bvec,
                                                    float* __restrict__ out) {
    const int d = blockIdx.x;
    const int np = blockIdx.y;
    const float wx = g_WX[d];
    const float wy = g_WY[d];
    const float e = g_E[np * CCH + d] + bvec[d];
    const size_t base = ((size_t)np * CCH + d) * HW;
    for (int p = threadIdx.x; p < HW; p += 256) {
        float gx = (float)(p % WDIM) / 60.0f;
        float gy = (float)(p / WDIM) / 60.0f;
        out[base + p] = x[base + p] + gx * wx + gy * wy + e;
    }
}

// ---------------- launch ----------------
extern "C" void kernel_launch(void* const* d_in, const int* in_sizes, int n_in,
                              void* d_out, int out_size) {
    (void)in_sizes; (void)n_in; (void)out_size;
    const float* x = (const float*)d_in[0];
    const float* W = (const float*)d_in[1];
    const float* b = (const float*)d_in[2];
    float* out = (float*)d_out;

    gemm_kernel<<<dim3(NBX, NBX, NBATCH), 256>>>(x);
    rowfin_kernel<<<dim3(LCPARTS, NBATCH), 256>>>();
    colfin_kernel<<<dim3(LCPARTS, NBATCH), 256>>>();
    bound_kernel<<<NBATCH, 256>>>();
    collect_kernel<<<dim3(HW, NBATCH), 128>>>();
    select_kernel<<<NBATCH, 256>>>();
    prep_kernel<<<8, 128>>>(W);
    final_kernel<<<dim3(CCH, 8), 256>>>(x, b, out);
}

// round 4
// speedup vs baseline: 18.2156x; 1.4519x over previous
#include <cuda_runtime.h>
#include <math_constants.h>
#include <stdint.h>

#define HW    3600
#define WDIM  60
#define CCH   128
#define NBATCH 4
#define KTOP  100
#define CAP   65536
#define NBX   29          // ceil(3600/128)
#define BK    16
#define SPAD  136         // smem row pitch (conflict-free fragment loads)
#define LCPARTS 15

// ---------------- device scratch ----------------
__device__ float g_sm[(size_t)NBATCH * HW * HW];   // 207 MB
__device__ float g_rp[NBATCH * NBX * HW];
__device__ float g_cp[NBATCH * NBX * HW];
__device__ float g_vp[NBATCH * NBX * HW];
__device__ float g_LR[NBATCH * HW];
__device__ float g_LC[NBATCH * HW];
__device__ float g_vmax[NBATCH * HW];
__device__ float g_lcmin_part[NBATCH * LCPARTS];
__device__ float g_lcmax_part[NBATCH * LCPARTS];
__device__ float g_thrv[NBATCH];
__device__ float g_lcmin[NBATCH];
__device__ int   g_cnt[NBATCH];
__device__ float g_cv[NBATCH * CAP];
__device__ int   g_ci[NBATCH * CAP];
__device__ int   g_topi[NBATCH * KTOP];
__device__ float g_E[8 * CCH];
__device__ float g_WX[CCH];
__device__ float g_WY[CCH];

// ---------------- helpers ----------------
__device__ __forceinline__ void cp16(float* dst_smem, const float* src, bool ok) {
    unsigned d = (unsigned)__cvta_generic_to_shared(dst_smem);
    int sz = ok ? 16 : 0;
    asm volatile("cp.async.ca.shared.global [%0], [%1], 16, %2;\n" :: "r"(d), "l"(src), "r"(sz));
}
__device__ __forceinline__ void cp_commit() { asm volatile("cp.async.commit_group;\n"); }
__device__ __forceinline__ void cp_wait0()  { asm volatile("cp.async.wait_group 0;\n"); }

__device__ __forceinline__ void mma_tf32(float c[4], const unsigned a[4], const unsigned b[2]) {
    asm volatile(
        "mma.sync.aligned.m16n8k8.row.col.f32.tf32.tf32.f32 "
        "{%0,%1,%2,%3}, {%4,%5,%6,%7}, {%8,%9}, {%0,%1,%2,%3};"
        : "+f"(c[0]), "+f"(c[1]), "+f"(c[2]), "+f"(c[3])
        : "r"(a[0]), "r"(a[1]), "r"(a[2]), "r"(a[3]), "r"(b[0]), "r"(b[1]));
}

__device__ __forceinline__ unsigned mono_bits(float f) {
    unsigned b = __float_as_uint(f);
    return (b & 0x80000000u) ? ~b : (b | 0x80000000u);
}

// split fp32 -> tf32 hi (truncated) + lo (exact remainder)
__device__ __forceinline__ void tf32split(float a, unsigned& hi, unsigned& lo) {
    hi = __float_as_uint(a) & 0xFFFFE000u;
    lo = __float_as_uint(a - __uint_as_float(hi));
}

// ---------------- GEMM (tf32 x3 mma) + fused exp-stats epilogue ----------------
// 512 threads, 16 warps in 4x4 grid, warp tile 32x32, block tile 128x128.
__global__ __launch_bounds__(512, 1) void gemm_kernel(const float* __restrict__ x) {
    __shared__ float As[2][BK][SPAD];
    __shared__ float Bs[2][BK][SPAD];
    __shared__ float s_rs[4][128];
    __shared__ float s_rm[4][128];
    __shared__ float s_cs[4][128];

    const int n  = blockIdx.z;
    const int l0 = blockIdx.y * 128;
    const int s0 = blockIdx.x * 128;
    const float* A = x + (size_t)n * CCH * HW;
    const float* B = x + (size_t)(n + NBATCH) * CCH * HW;
    const int tid = threadIdx.x;
    const int lane = tid & 31;
    const int wid = tid >> 5;
    const int g = lane >> 2, tig = lane & 3;
    const int wm = wid & 3, wn = wid >> 2;
    const int rb = wm * 32, cb = wn * 32;

    float acc[2][4][4];
#pragma unroll
    for (int mi = 0; mi < 2; mi++)
#pragma unroll
        for (int ni = 0; ni < 4; ni++)
#pragma unroll
            for (int q = 0; q < 4; q++) acc[mi][ni][q] = 0.0f;

    // prefetch chunk 0 (512 threads -> one float4 each for A and B)
    {
        const int d = tid >> 5;
        const int c4 = (lane) << 2;
        int colA = l0 + c4; bool okA = colA < HW;
        cp16(&As[0][d][c4], A + (size_t)d * HW + (okA ? colA : 0), okA);
        int colB = s0 + c4; bool okB = colB < HW;
        cp16(&Bs[0][d][c4], B + (size_t)d * HW + (okB ? colB : 0), okB);
    }
    cp_commit();

    for (int c = 0; c < CCH / BK; c++) {
        cp_wait0();
        __syncthreads();
        if (c < CCH / BK - 1) {
            const int kc = c + 1, st = (c + 1) & 1;
            const int d = tid >> 5;
            const int c4 = (lane) << 2;
            int colA = l0 + c4; bool okA = colA < HW;
            cp16(&As[st][d][c4], A + (size_t)(kc * BK + d) * HW + (okA ? colA : 0), okA);
            int colB = s0 + c4; bool okB = colB < HW;
            cp16(&Bs[st][d][c4], B + (size_t)(kc * BK + d) * HW + (okB ? colB : 0), okB);
            cp_commit();
        }
        const int st = c & 1;
#pragma unroll
        for (int ks = 0; ks < BK; ks += 8) {
            const int k0 = ks + tig;
            unsigned ah[2][4], al[2][4], bh[4][2], bl[4][2];
#pragma unroll
            for (int mi = 0; mi < 2; mi++) {
                const int m = rb + mi * 16 + g;
                tf32split(As[st][k0][m],         ah[mi][0], al[mi][0]);
                tf32split(As[st][k0][m + 8],     ah[mi][1], al[mi][1]);
                tf32split(As[st][k0 + 4][m],     ah[mi][2], al[mi][2]);
                tf32split(As[st][k0 + 4][m + 8], ah[mi][3], al[mi][3]);
            }
#pragma unroll
            for (int ni = 0; ni < 4; ni++) {
                const int nn = cb + ni * 8 + g;
                tf32split(Bs[st][k0][nn],     bh[ni][0], bl[ni][0]);
                tf32split(Bs[st][k0 + 4][nn], bh[ni][1], bl[ni][1]);
            }
#pragma unroll
            for (int mi = 0; mi < 2; mi++)
#pragma unroll
                for (int ni = 0; ni < 4; ni++) {
                    mma_tf32(acc[mi][ni], ah[mi], bl[ni]);
                    mma_tf32(acc[mi][ni], al[mi], bh[ni]);
                    mma_tf32(acc[mi][ni], ah[mi], bh[ni]);
                }
        }
    }

    // ---- epilogue: scale, store, exp stats ----
    const float inv = 1.0f / 12.8f;
    float rsum[2][2], rmax[2][2], csum[4][2];
#pragma unroll
    for (int i = 0; i < 2; i++)
#pragma unroll
        for (int r = 0; r < 2; r++) {
            rsum[i][r] = 0.0f; rmax[i][r] = -CUDART_INF_F;
        }
#pragma unroll
    for (int i = 0; i < 4; i++) { csum[i][0] = 0.0f; csum[i][1] = 0.0f; }

#pragma unroll
    for (int mi = 0; mi < 2; mi++) {
        const int row0 = l0 + rb + mi * 16 + g;
        const int row1 = row0 + 8;
        const bool rv0 = row0 < HW, rv1 = row1 < HW;
        float* orow0 = g_sm + ((size_t)(n * HW + row0)) * HW;
        float* orow1 = g_sm + ((size_t)(n * HW + row1)) * HW;
#pragma unroll
        for (int ni = 0; ni < 4; ni++) {
            const int sc0 = s0 + cb + ni * 8 + tig * 2;
            const bool cv0 = sc0 < HW, cv1 = (sc0 + 1) < HW;
            float v0 = acc[mi][ni][0] * inv;
            float v1 = acc[mi][ni][1] * inv;
            float v2 = acc[mi][ni][2] * inv;
            float v3 = acc[mi][ni][3] * inv;
            if (rv0 && cv0) *reinterpret_cast<float2*>(orow0 + sc0) = make_float2(v0, v1);
            if (rv1 && cv0) *reinterpret_cast<float2*>(orow1 + sc0) = make_float2(v2, v3);
            float e0 = cv0 ? __expf(v0) : 0.0f;
            float e1 = cv1 ? __expf(v1) : 0.0f;
            float e2 = cv0 ? __expf(v2) : 0.0f;
            float e3 = cv1 ? __expf(v3) : 0.0f;
            rsum[mi][0] += e0 + e1;
            rsum[mi][1] += e2 + e3;
            rmax[mi][0] = fmaxf(rmax[mi][0], fmaxf(cv0 ? v0 : -CUDART_INF_F, cv1 ? v1 : -CUDART_INF_F));
            rmax[mi][1] = fmaxf(rmax[mi][1], fmaxf(cv0 ? v2 : -CUDART_INF_F, cv1 ? v3 : -CUDART_INF_F));
            csum[ni][0] += (rv0 ? e0 : 0.0f) + (rv1 ? e2 : 0.0f);
            csum[ni][1] += (rv0 ? e1 : 0.0f) + (rv1 ? e3 : 0.0f);
        }
    }

    // row reduce over tig (lane bits 0,1)
#pragma unroll
    for (int m = 1; m < 4; m <<= 1) {
#pragma unroll
        for (int mi = 0; mi < 2; mi++)
#pragma unroll
            for (int r = 0; r < 2; r++) {
                rsum[mi][r] += __shfl_xor_sync(0xffffffffu, rsum[mi][r], m);
                rmax[mi][r] = fmaxf(rmax[mi][r], __shfl_xor_sync(0xffffffffu, rmax[mi][r], m));
            }
    }
    if (tig == 0) {
#pragma unroll
        for (int mi = 0; mi < 2; mi++) {
            const int rr = rb + mi * 16 + g;
            s_rs[wn][rr] = rsum[mi][0];
            s_rs[wn][rr + 8] = rsum[mi][1];
            s_rm[wn][rr] = rmax[mi][0];
            s_rm[wn][rr + 8] = rmax[mi][1];
        }
    }
    // col reduce over g (lane bits 2,3,4)
#pragma unroll
    for (int m = 4; m < 32; m <<= 1) {
#pragma unroll
        for (int ni = 0; ni < 4; ni++)
#pragma unroll
            for (int q = 0; q < 2; q++)
                csum[ni][q] += __shfl_xor_sync(0xffffffffu, csum[ni][q], m);
    }
    if (g == 0) {
#pragma unroll
        for (int ni = 0; ni < 4; ni++) {
            s_cs[wm][cb + ni * 8 + tig * 2]     = csum[ni][0];
            s_cs[wm][cb + ni * 8 + tig * 2 + 1] = csum[ni][1];
        }
    }
    __syncthreads();
    if (tid < 128) {
        float rs = 0.0f, rm = -CUDART_INF_F;
#pragma unroll
        for (int w = 0; w < 4; w++) { rs += s_rs[w][tid]; rm = fmaxf(rm, s_rm[w][tid]); }
        if (l0 + tid < HW) {
            g_rp[(n * NBX + blockIdx.x) * HW + l0 + tid] = rs;
            g_vp[(n * NBX + blockIdx.x) * HW + l0 + tid] = rm;
        }
        float cs = 0.0f;
#pragma unroll
        for (int w = 0; w < 4; w++) cs += s_cs[w][tid];
        if (s0 + tid < HW)
            g_cp[(n * NBX + blockIdx.y) * HW + s0 + tid] = cs;
    }
}

// ---------------- merge: LR, vmax ----------------
__global__ __launch_bounds__(256) void rowfin_kernel() {
    const int n = blockIdx.y;
    const int l = blockIdx.x * 256 + threadIdx.x;
    if (l >= HW) return;
    float s = 0.0f, m = -CUDART_INF_F;
#pragma unroll
    for (int b = 0; b < NBX; b++) {
        s += g_rp[(n * NBX + b) * HW + l];
        m = fmaxf(m, g_vp[(n * NBX + b) * HW + l]);
    }
    g_LR[n * HW + l] = logf(s);
    g_vmax[n * HW + l] = m;
}

// ---------------- merge: LC + per-block min/max ----------------
__global__ __launch_bounds__(256) void colfin_kernel() {
    const int n = blockIdx.y;
    const int s = blockIdx.x * 256 + threadIdx.x;
    __shared__ float mn[256], mx[256];
    float lo = CUDART_INF_F, hi = -CUDART_INF_F;
    if (s < HW) {
        float acc = 0.0f;
#pragma unroll
        for (int b = 0; b < NBX; b++) acc += g_cp[(n * NBX + b) * HW + s];
        float v = logf(acc);
        g_LC[n * HW + s] = v;
        lo = v; hi = v;
    }
    const int tid = threadIdx.x;
    mn[tid] = lo; mx[tid] = hi;
    __syncthreads();
    for (int o = 128; o > 0; o >>= 1) {
        if (tid < o) {
            mn[tid] = fminf(mn[tid], mn[tid + o]);
            mx[tid] = fmaxf(mx[tid], mx[tid + o]);
        }
        __syncthreads();
    }
    if (tid == 0) {
        g_lcmin_part[n * LCPARTS + blockIdx.x] = mn[0];
        g_lcmax_part[n * LCPARTS + blockIdx.x] = mx[0];
    }
}

// ---------------- threshold from per-row score lower bounds ----------------
__global__ __launch_bounds__(256) void bound_kernel() {
    const int n = blockIdx.x;
    const int tid = threadIdx.x;
    __shared__ float s_lcmax;
    __shared__ float red1[256], red2[256];
    __shared__ int hist[2048];
    __shared__ unsigned ssum[256];
    __shared__ float s_lmn, s_lmx;

    if (tid == 0) {
        float mn = CUDART_INF_F, mx = -CUDART_INF_F;
        for (int i = 0; i < LCPARTS; i++) {
            mn = fminf(mn, g_lcmin_part[n * LCPARTS + i]);
            mx = fmaxf(mx, g_lcmax_part[n * LCPARTS + i]);
        }
        g_lcmin[n] = mn;
        s_lcmax = mx;
        g_cnt[n] = 0;
    }
    __syncthreads();
    const float lcmax = s_lcmax;

    float lmn = CUDART_INF_F, lmx = -CUDART_INF_F;
    for (int l = tid; l < HW; l += 256) {
        float L = fmaf(2.0f, g_vmax[n * HW + l], -g_LR[n * HW + l]) - lcmax;
        lmn = fminf(lmn, L); lmx = fmaxf(lmx, L);
    }
    red1[tid] = lmn; red2[tid] = lmx;
    __syncthreads();
    for (int o = 128; o > 0; o >>= 1) {
        if (tid < o) {
            red1[tid] = fminf(red1[tid], red1[tid + o]);
            red2[tid] = fmaxf(red2[tid], red2[tid + o]);
        }
        __syncthreads();
    }
    if (tid == 0) { s_lmn = red1[0]; s_lmx = red2[0]; }
    __syncthreads();
    const float Lmn = s_lmn;
    const float binw = (s_lmx - Lmn) * (1.0f / 2048.0f);
    if (binw < 1e-30f) {
        if (tid == 0) g_thrv[n] = Lmn;
        return;
    }
    for (int i = tid; i < 2048; i += 256) hist[i] = 0;
    __syncthreads();
    for (int l = tid; l < HW; l += 256) {
        float L = fmaf(2.0f, g_vmax[n * HW + l], -g_LR[n * HW + l]) - lcmax;
        int b = (int)((L - Lmn) / binw);
        b = max(0, min(2047, b));
        atomicAdd(&hist[b], 1);
    }
    __syncthreads();
    unsigned csum = 0;
#pragma unroll
    for (int i = 0; i < 8; i++) csum += (unsigned)hist[tid * 8 + i];
    ssum[tid] = csum;
    __syncthreads();
    for (int off = 1; off < 256; off <<= 1) {
        unsigned v = (tid + off < 256) ? ssum[tid + off] : 0u;
        __syncthreads();
        ssum[tid] += v;
        __syncthreads();
    }
    unsigned mine = ssum[tid];
    unsigned next = (tid < 255) ? ssum[tid + 1] : 0u;
    if (mine >= KTOP && next < KTOP) {
        unsigned cum = next;
        int b = tid * 8 + 7;
        for (; b > tid * 8; b--) {
            cum += (unsigned)hist[b];
            if (cum >= KTOP) break;
        }
        g_thrv[n] = Lmn + (float)(b - 1) * binw;   // one-bin safety margin
    }
}

// ---------------- collect candidates (only flagged rows) ----------------
__global__ __launch_bounds__(128) void collect_kernel() {
    const int n = blockIdx.y, l = blockIdx.x;
    const float t = g_thrv[n];
    const float LR = g_LR[n * HW + l];
    const float Bnd = fmaf(2.0f, g_vmax[n * HW + l], -LR) - g_lcmin[n];
    if (Bnd < t) return;
    const float* row = g_sm + ((size_t)(n * HW + l)) * HW;
    const float* LC = g_LC + n * HW;
    for (int s4 = threadIdx.x * 4; s4 < HW; s4 += 128 * 4) {
        float4 v = *reinterpret_cast<const float4*>(row + s4);
        float4 c = *reinterpret_cast<const float4*>(LC + s4);
        float sc[4];
        sc[0] = fmaf(2.0f, v.x, -LR) - c.x;
        sc[1] = fmaf(2.0f, v.y, -LR) - c.y;
        sc[2] = fmaf(2.0f, v.z, -LR) - c.z;
        sc[3] = fmaf(2.0f, v.w, -LR) - c.w;
#pragma unroll
        for (int q = 0; q < 4; q++) {
            if (sc[q] >= t) {
                int p = atomicAdd(&g_cnt[n], 1);
                if (p < CAP) {
                    g_cv[n * CAP + p] = sc[q];
                    g_ci[n * CAP + p] = l * HW + s4 + q;
                }
            }
        }
    }
}

// ---------------- top-100: smem bitonic sort on packed keys ----------------
__global__ __launch_bounds__(256) void select_kernel() {
    const int n = blockIdx.x;
    const int tid = threadIdx.x;
    int cnt = g_cnt[n];
    if (cnt > CAP) cnt = CAP;
    float* cv = g_cv + n * CAP;
    int* ci = g_ci + n * CAP;

    if (cnt <= 2048) {
        __shared__ unsigned long long key[2048];
        for (int i = tid; i < 2048; i += 256) {
            unsigned long long k = 0ull;
            if (i < cnt)
                k = ((unsigned long long)mono_bits(cv[i]) << 32) |
                    (unsigned long long)(0xFFFFFFFFu - (unsigned)ci[i]);
            key[i] = k;
        }
        __syncthreads();
        for (int kk = 2; kk <= 2048; kk <<= 1) {
            for (int j = kk >> 1; j > 0; j >>= 1) {
                for (int i = tid; i < 2048; i += 256) {
                    int ixj = i ^ j;
                    if (ixj > i) {
                        bool dirDesc = ((i & kk) == 0);
                        unsigned long long a = key[i], b = key[ixj];
                        if ((a < b) == dirDesc) { key[i] = b; key[ixj] = a; }
                    }
                }
                __syncthreads();
            }
        }
        if (tid < KTOP)
            g_topi[n * KTOP + tid] = (int)(0xFFFFFFFFu - (unsigned)(key[tid] & 0xFFFFFFFFull));
        return;
    }

    // fallback: iterative argmax
    __shared__ float sv[256];
    __shared__ int si[256];
    __shared__ int sp[256];
    for (int k = 0; k < KTOP; k++) {
        float bv = -CUDART_INF_F; int bi = 0x7FFFFFFF; int bp = -1;
        for (int j = tid; j < cnt; j += 256) {
            float v = cv[j]; int idx = ci[j];
            if (v > bv || (v == bv && idx < bi)) { bv = v; bi = idx; bp = j; }
        }
        sv[tid] = bv; si[tid] = bi; sp[tid] = bp;
        __syncthreads();
        for (int o = 128; o > 0; o >>= 1) {
            if (tid < o) {
                if (sv[tid + o] > sv[tid] || (sv[tid + o] == sv[tid] && si[tid + o] < si[tid])) {
                    sv[tid] = sv[tid + o]; si[tid] = si[tid + o]; sp[tid] = sp[tid + o];
                }
            }
            __syncthreads();
        }
        if (tid == 0) {
            g_topi[n * KTOP + k] = si[0];
            if (sp[0] >= 0) cv[sp[0]] = -CUDART_INF_F;
        }
        __syncthreads();
    }
}

// ---------------- embedding closed form ----------------
__global__ __launch_bounds__(128) void prep_kernel(const float* __restrict__ W) {
    const int np = blockIdx.x;
    const int d = threadIdx.x;
    const int n = np & 3;
    const bool side1 = (np >= 4);
    float S = 0.0f, wx = 0.0f, wy = 0.0f;
    for (int k = 0; k < KTOP; k++) {
        int idx = g_topi[n * KTOP + k];
        int r = side1 ? (idx % HW) : (idx / HW);
        float cx = (float)(r % WDIM) / 60.0f;
        float cy = (float)(r / WDIM) / 60.0f;
        float w0 = W[d * (2 * KTOP) + 2 * k];
        float w1 = W[d * (2 * KTOP) + 2 * k + 1];
        S = fmaf(w0, cx, S);
        S = fmaf(w1, cy, S);
        wx += w0; wy += w1;
    }
    g_E[np * CCH + d] = -S;
    if (np == 0) { g_WX[d] = wx; g_WY[d] = wy; }
}

__global__ __launch_bounds__(256) void final_kernel(const float* __restrict__ x,
                                                    const float* __restrict__ bvec,
                                                    float* __restrict__ out) {
    const int d = blockIdx.x;
    const int np = blockIdx.y;
    const float wx = g_WX[d];
    const float wy = g_WY[d];
    const float e = g_E[np * CCH + d] + bvec[d];
    const size_t base = ((size_t)np * CCH + d) * HW;
    for (int p = threadIdx.x; p < HW; p += 256) {
        float gx = (float)(p % WDIM) / 60.0f;
        float gy = (float)(p / WDIM) / 60.0f;
        out[base + p] = x[base + p] + gx * wx + gy * wy + e;
    }
}

// ---------------- launch ----------------
extern "C" void kernel_launch(void* const* d_in, const int* in_sizes, int n_in,
                              void* d_out, int out_size) {
    (void)in_sizes; (void)n_in; (void)out_size;
    const float* x = (const float*)d_in[0];
    const float* W = (const float*)d_in[1];
    const float* b = (const float*)d_in[2];
    float* out = (float*)d_out;

    gemm_kernel<<<dim3(NBX, NBX, NBATCH), 512>>>(x);
    rowfin_kernel<<<dim3(LCPARTS, NBATCH), 256>>>();
    colfin_kernel<<<dim3(LCPARTS, NBATCH), 256>>>();
    bound_kernel<<<NBATCH, 256>>>();
    collect_kernel<<<dim3(HW, NBATCH), 128>>>();
    select_kernel<<<NBATCH, 256>>>();
    prep_kernel<<<8, 128>>>(W);
    final_kernel<<<dim3(CCH, 8), 256>>>(x, b, out);
}